// round 7
// baseline (speedup 1.0000x reference)
#include <cuda_runtime.h>
#include <cuda_bf16.h>

// B=64, H=W=1024, patch=64 -> 16x16 = 256 patches/img.
// final = mean_b( max_patch( mean_{64x64} |o - t| ) )
//
// One block per PAIR of horizontally adjacent patches (grid 8192, 256 thr).
// Thread owns float4-col (tid&31) and row-group (tid>>5); 16 loads issued in
// two batches of 8 (4 o + 4 t) to stay <=64 regs -> 4 CTAs/SM (50% occ) while
// keeping 32KB/SM in flight.

#define B 64
#define HW 1024
#define P 64
#define NBLOCKS (B * 16 * 8)            // 8192
#define PATCH_ELEMS (P * P)             // 4096

__device__ unsigned int g_img_max[B];   // zero-init; re-zeroed by last block
__device__ unsigned int g_counter;      // monotone, wrap-safe

__global__ __launch_bounds__(256, 4) void patch_loss_pair_kernel(
    const float* __restrict__ o, const float* __restrict__ t,
    float* __restrict__ out)
{
    const int blk  = blockIdx.x;          // 0..8191
    const int img  = blk >> 7;
    const int ph   = (blk >> 3) & 15;
    const int pair = blk & 7;             // patch-col pair 0..7

    const size_t base = (size_t)img * (HW * HW) + (size_t)ph * (P * HW)
                      + (size_t)pair * 128;
    const float4* __restrict__ o4 = reinterpret_cast<const float4*>(o + base);
    const float4* __restrict__ t4 = reinterpret_cast<const float4*>(t + base);

    const int tid = threadIdx.x;
    const int col = tid & 31;             // float4 col within pair (== lane)
    const int rg  = tid >> 5;             // row group 0..7
    const int off0 = rg * 256 + col;      // rows rg + i*8; row stride 256 f4

    float acc0 = 0.0f, acc1 = 0.0f;

    // Batch 1: rows rg + {0,8,16,24}
    {
        float4 a0 = __ldcs(&o4[off0]);
        float4 a1 = __ldcs(&o4[off0 + 2048]);
        float4 a2 = __ldcs(&o4[off0 + 4096]);
        float4 a3 = __ldcs(&o4[off0 + 6144]);
        float4 b0 = __ldcs(&t4[off0]);
        float4 b1 = __ldcs(&t4[off0 + 2048]);
        float4 b2 = __ldcs(&t4[off0 + 4096]);
        float4 b3 = __ldcs(&t4[off0 + 6144]);
        acc0 += fabsf(a0.x - b0.x) + fabsf(a0.y - b0.y)
              + fabsf(a0.z - b0.z) + fabsf(a0.w - b0.w);
        acc1 += fabsf(a1.x - b1.x) + fabsf(a1.y - b1.y)
              + fabsf(a1.z - b1.z) + fabsf(a1.w - b1.w);
        acc0 += fabsf(a2.x - b2.x) + fabsf(a2.y - b2.y)
              + fabsf(a2.z - b2.z) + fabsf(a2.w - b2.w);
        acc1 += fabsf(a3.x - b3.x) + fabsf(a3.y - b3.y)
              + fabsf(a3.z - b3.z) + fabsf(a3.w - b3.w);
    }
    // Batch 2: rows rg + {32,40,48,56}
    {
        float4 a0 = __ldcs(&o4[off0 + 8192]);
        float4 a1 = __ldcs(&o4[off0 + 10240]);
        float4 a2 = __ldcs(&o4[off0 + 12288]);
        float4 a3 = __ldcs(&o4[off0 + 14336]);
        float4 b0 = __ldcs(&t4[off0 + 8192]);
        float4 b1 = __ldcs(&t4[off0 + 10240]);
        float4 b2 = __ldcs(&t4[off0 + 12288]);
        float4 b3 = __ldcs(&t4[off0 + 14336]);
        acc0 += fabsf(a0.x - b0.x) + fabsf(a0.y - b0.y)
              + fabsf(a0.z - b0.z) + fabsf(a0.w - b0.w);
        acc1 += fabsf(a1.x - b1.x) + fabsf(a1.y - b1.y)
              + fabsf(a1.z - b1.z) + fabsf(a1.w - b1.w);
        acc0 += fabsf(a2.x - b2.x) + fabsf(a2.y - b2.y)
              + fabsf(a2.z - b2.z) + fabsf(a2.w - b2.w);
        acc1 += fabsf(a3.x - b3.x) + fabsf(a3.y - b3.y)
              + fabsf(a3.z - b3.z) + fabsf(a3.w - b3.w);
    }
    float acc = acc0 + acc1;

    // Reduce within each 16-lane half (one patch per half).
#pragma unroll
    for (int s = 8; s > 0; s >>= 1)
        acc += __shfl_xor_sync(0xFFFFFFFFu, acc, s);

    __shared__ float warp_sums[2][8];
    __shared__ bool s_is_last;
    const int lane = tid & 31;
    const int wid = tid >> 5;
    if (lane == 0)  warp_sums[0][wid] = acc;
    if (lane == 16) warp_sums[1][wid] = acc;
    __syncthreads();

    if (tid == 0) {
        float v0 = 0.f, v1 = 0.f;
#pragma unroll
        for (int w = 0; w < 8; w++) { v0 += warp_sums[0][w]; v1 += warp_sums[1][w]; }
        atomicMax(&g_img_max[img], __float_as_uint(v0));  // >=0: bits monotone
        atomicMax(&g_img_max[img], __float_as_uint(v1));
        __threadfence();
        unsigned int old = atomicAdd(&g_counter, 1u);
        s_is_last = ((old % NBLOCKS) == (NBLOCKS - 1));
    }
    __syncthreads();

    if (s_is_last) {
        __threadfence();
        __shared__ float red[2];
        if (wid < 2) {
            int i = wid * 32 + lane;
            unsigned int bits = atomicOr(&g_img_max[i], 0u);
            float m = __uint_as_float(bits);
#pragma unroll
            for (int s = 16; s > 0; s >>= 1)
                m += __shfl_xor_sync(0xFFFFFFFFu, m, s);
            if (lane == 0) red[wid] = m;
        }
        __syncthreads();
        if (tid == 0)
            *out = (red[0] + red[1]) * (1.0f / (float)PATCH_ELEMS / (float)B);
        __syncthreads();
        if (tid < B) g_img_max[tid] = 0u;   // reset for next replay
    }
}

extern "C" void kernel_launch(void* const* d_in, const int* in_sizes, int n_in,
                              void* d_out, int out_size)
{
    const float* o = (const float*)d_in[0];
    const float* t = (const float*)d_in[1];
    float* out = (float*)d_out;
    patch_loss_pair_kernel<<<NBLOCKS, 256>>>(o, t, out);
}

// round 8
// speedup vs baseline: 1.0333x; 1.0333x over previous
#include <cuda_runtime.h>
#include <cuda_bf16.h>

// B=64, H=W=1024, patch=64 -> 16x16 = 256 patches/img.
// final = mean_b( max_patch( mean_{64x64} |o - t| ) )
//
// One block per QUAD of horizontally adjacent patches (grid 4096, 256 thr),
// processed as two sequential pair-tiles. Each pair-tile uses the R6 engine:
// all 16 LDG.128 front-batched (8 o + 8 t) before any math. Register batch
// is reused across tiles -> regs ~72, 3 CTAs/SM, 48KB in flight per SM.
// Lane==col: lanes 0-15 hold even patch, 16-31 odd patch of each pair.

#define B 64
#define HW 1024
#define P 64
#define NBLOCKS (B * 16 * 4)            // 4096
#define PATCH_ELEMS (P * P)             // 4096

__device__ unsigned int g_img_max[B];   // zero-init; re-zeroed by last block
__device__ unsigned int g_counter;      // monotone, wrap-safe

__device__ __forceinline__ float pair_tile_sum(
    const float4* __restrict__ o4, const float4* __restrict__ t4, int off0)
{
    float4 av[8], bv[8];
#pragma unroll
    for (int i = 0; i < 8; i++) av[i] = __ldcs(&o4[off0 + i * 2048]);
#pragma unroll
    for (int i = 0; i < 8; i++) bv[i] = __ldcs(&t4[off0 + i * 2048]);
    float acc = 0.0f;
#pragma unroll
    for (int i = 0; i < 8; i++) {
        acc += fabsf(av[i].x - bv[i].x) + fabsf(av[i].y - bv[i].y)
             + fabsf(av[i].z - bv[i].z) + fabsf(av[i].w - bv[i].w);
    }
    // Reduce within each 16-lane half (one patch per half).
#pragma unroll
    for (int s = 8; s > 0; s >>= 1)
        acc += __shfl_xor_sync(0xFFFFFFFFu, acc, s);
    return acc;
}

__global__ __launch_bounds__(256, 3) void patch_loss_quad_kernel(
    const float* __restrict__ o, const float* __restrict__ t,
    float* __restrict__ out)
{
    const int blk  = blockIdx.x;          // 0..4095
    const int img  = blk >> 6;            // /64
    const int ph   = (blk >> 2) & 15;
    const int quad = blk & 3;             // patch-col quad 0..3 (256 floats)

    const size_t base = (size_t)img * (HW * HW) + (size_t)ph * (P * HW)
                      + (size_t)quad * 256;
    const float4* __restrict__ o4 = reinterpret_cast<const float4*>(o + base);
    const float4* __restrict__ t4 = reinterpret_cast<const float4*>(t + base);

    const int tid = threadIdx.x;
    const int col = tid & 31;             // float4 col within pair (== lane)
    const int rg  = tid >> 5;             // row group 0..7
    const int off0 = rg * 256 + col;      // rows rg + i*8; row stride 256 f4

    // Tile 0: pair (patch 2*quad, 2*quad+1); Tile 1: next pair (+32 f4 cols)
    float accA = pair_tile_sum(o4, t4, off0);
    float accB = pair_tile_sum(o4, t4, off0 + 32);

    __shared__ float warp_sums[4][8];
    __shared__ bool s_is_last;
    const int lane = tid & 31;
    const int wid = tid >> 5;
    if (lane == 0)  { warp_sums[0][wid] = accA; warp_sums[2][wid] = accB; }
    if (lane == 16) { warp_sums[1][wid] = accA; warp_sums[3][wid] = accB; }
    __syncthreads();

    if (tid == 0) {
        float v0 = 0.f, v1 = 0.f, v2 = 0.f, v3 = 0.f;
#pragma unroll
        for (int w = 0; w < 8; w++) {
            v0 += warp_sums[0][w]; v1 += warp_sums[1][w];
            v2 += warp_sums[2][w]; v3 += warp_sums[3][w];
        }
        // take max locally first: 1 atomic per block instead of 4
        float vm = fmaxf(fmaxf(v0, v1), fmaxf(v2, v3));
        atomicMax(&g_img_max[img], __float_as_uint(vm));  // >=0: bits monotone
        __threadfence();
        unsigned int old = atomicAdd(&g_counter, 1u);
        s_is_last = ((old % NBLOCKS) == (NBLOCKS - 1));
    }
    __syncthreads();

    if (s_is_last) {
        __threadfence();
        __shared__ float red[2];
        if (wid < 2) {
            int i = wid * 32 + lane;                     // 0..63
            unsigned int bits = atomicOr(&g_img_max[i], 0u);
            float m = __uint_as_float(bits);
#pragma unroll
            for (int s = 16; s > 0; s >>= 1)
                m += __shfl_xor_sync(0xFFFFFFFFu, m, s);
            if (lane == 0) red[wid] = m;
        }
        __syncthreads();
        if (tid == 0)
            *out = (red[0] + red[1]) * (1.0f / (float)PATCH_ELEMS / (float)B);
        __syncthreads();
        if (tid < B) g_img_max[tid] = 0u;   // reset for next replay
    }
}

extern "C" void kernel_launch(void* const* d_in, const int* in_sizes, int n_in,
                              void* d_out, int out_size)
{
    const float* o = (const float*)d_in[0];
    const float* t = (const float*)d_in[1];
    float* out = (float*)d_out;
    patch_loss_quad_kernel<<<NBLOCKS, 256>>>(o, t, out);
}